// round 2
// baseline (speedup 1.0000x reference)
#include <cuda_runtime.h>

#define D0 64
#define D1 128
#define NMAX 100000
#define EMAX 1600000
#define RPB 8   // rows per warp per iteration in GEMM kernels

// Scratch (device globals; allocation in kernel_launch is forbidden)
__device__ __align__(16) float g_deg[NMAX];          // 0.4 MB
__device__ __align__(16) float g_agg1[NMAX * D0];    // 25.6 MB
__device__ __align__(16) float g_agg2[NMAX * D0];    // 25.6 MB
__device__ __align__(16) float g_p[NMAX * D0];       // 25.6 MB  (p = h @ W2)
__device__ __align__(16) float g_h[NMAX * D1];       // 51.2 MB  (relu layer-1 output)
__device__ __align__(16) int   g_idx[2 * EMAX];      // 12.8 MB  (row, col as int32)
__device__ int g_is64;

// ---------------------------------------------------------------------------
// Detect whether edge_index was delivered as int64 or int32.
// int64 values < 2^31: every odd 32-bit word is 0. Random int32 indices: no.
// ---------------------------------------------------------------------------
__global__ void detect_k(const int* __restrict__ ei_raw, int total_i32) {
    __shared__ int any_nz;
    if (threadIdx.x == 0) any_nz = 0;
    __syncthreads();
    int limit = total_i32 < 8192 ? total_i32 : 8192;
    for (int i = 2 * threadIdx.x + 1; i < limit; i += 2 * blockDim.x)
        if (ei_raw[i] != 0) any_nz = 1;
    __syncthreads();
    if (threadIdx.x == 0) g_is64 = any_nz ? 0 : 1;
}

__global__ void convert_k(const void* __restrict__ ei, int total) {
    int i = blockIdx.x * blockDim.x + threadIdx.x;
    if (i >= total) return;
    if (g_is64) g_idx[i] = (int)((const long long*)ei)[i];
    else        g_idx[i] = ((const int*)ei)[i];
}

// ---------------------------------------------------------------------------
// Zero deg + agg buffers (g_h / g_p are fully overwritten, no zero needed)
// ---------------------------------------------------------------------------
__global__ void zero_k(int Nn) {
    int tid = blockIdx.x * blockDim.x + threadIdx.x;
    float4 z = make_float4(0.f, 0.f, 0.f, 0.f);
    int tot = Nn * 16;  // float4 count per agg array
    if (tid < tot) {
        ((float4*)g_agg1)[tid] = z;
        ((float4*)g_agg2)[tid] = z;
    }
    if (tid < (Nn + 3) / 4) ((float4*)g_deg)[tid] = z;
}

// ---------------------------------------------------------------------------
// Scatter 1: agg1[row] += x[col] (64 floats/edge), fused degree count.
// 16 threads per edge, each handles one float4; vector red.global.add.v4.f32.
// ---------------------------------------------------------------------------
__global__ void scatter1_k(const float4* __restrict__ x4, int E) {
    long long tid = (long long)blockIdx.x * blockDim.x + threadIdx.x;
    int e = (int)(tid >> 4);
    if (e >= E) return;
    int c = (int)(tid & 15);
    int r  = g_idx[e];       // row
    int cl = g_idx[e + E];   // col
    float4 v = __ldg(&x4[cl * 16 + c]);
    float* d = g_agg1 + (long long)r * D0 + c * 4;
    asm volatile("red.global.add.v4.f32 [%0], {%1,%2,%3,%4};"
                 :: "l"(d), "f"(v.x), "f"(v.y), "f"(v.z), "f"(v.w) : "memory");
    if (c == 0) atomicAdd(g_deg + r, 1.0f);
}

// ---------------------------------------------------------------------------
// Scatter 2: agg2[row] += p[col] (64 floats/edge)
// ---------------------------------------------------------------------------
__global__ void scatter2_k(int E) {
    long long tid = (long long)blockIdx.x * blockDim.x + threadIdx.x;
    int e = (int)(tid >> 4);
    if (e >= E) return;
    int c = (int)(tid & 15);
    int r  = g_idx[e];
    int cl = g_idx[e + E];
    float4 v = __ldg(&((const float4*)g_p)[cl * 16 + c]);
    float* d = g_agg2 + (long long)r * D0 + c * 4;
    asm volatile("red.global.add.v4.f32 [%0], {%1,%2,%3,%4};"
                 :: "l"(d), "f"(v.x), "f"(v.y), "f"(v.z), "f"(v.w) : "memory");
}

// ---------------------------------------------------------------------------
// mm1: h = relu((agg1/deg + x) @ W1 + b1)   [N,64] -> [N,128]
// 128 threads/block = 4 warps. Each warp processes RPB rows per iteration.
// Lane j computes output columns 4j..4j+3 (float4 accumulators).
// ---------------------------------------------------------------------------
__global__ __launch_bounds__(128) void mm1_k(const float* __restrict__ x,
                                             const float* __restrict__ W1,
                                             const float* __restrict__ b1,
                                             int Nn) {
    __shared__ float sW1[D0 * D1];          // 32 KB, row-major [k][j]
    __shared__ float sb1[D1];
    __shared__ float st[4][RPB][D0];        // staged inputs, 8 KB

    int tid = threadIdx.x;
    for (int i = tid; i < D0 * D1; i += blockDim.x) sW1[i] = W1[i];
    if (tid < D1) sb1[tid] = b1[tid];
    __syncthreads();

    int warp = tid >> 5, lane = tid & 31;
    int nwarps = gridDim.x * 4;
    int gw = blockIdx.x * 4 + warp;
    float4 b4 = ((const float4*)sb1)[lane];

    for (int base = gw * RPB; base < Nn; base += nwarps * RPB) {
        // Stage t = agg1/deg + x (2 floats per lane per row)
        #pragma unroll
        for (int rr = 0; rr < RPB; rr++) {
            int r = base + rr;
            if (r < Nn) {
                float inv = 1.0f / fmaxf(g_deg[r], 1.0f);
                float2 a  = ((const float2*)g_agg1)[r * 32 + lane];
                float2 xx = __ldg(&((const float2*)x)[r * 32 + lane]);
                ((float2*)st[warp][rr])[lane] =
                    make_float2(a.x * inv + xx.x, a.y * inv + xx.y);
            }
        }
        __syncwarp();

        float4 acc[RPB];
        #pragma unroll
        for (int rr = 0; rr < RPB; rr++) acc[rr] = make_float4(0.f, 0.f, 0.f, 0.f);

        #pragma unroll 4
        for (int k = 0; k < D0; k++) {
            float4 w = ((const float4*)sW1)[k * 32 + lane];
            #pragma unroll
            for (int rr = 0; rr < RPB; rr++) {
                float t = st[warp][rr][k];
                acc[rr].x += t * w.x;
                acc[rr].y += t * w.y;
                acc[rr].z += t * w.z;
                acc[rr].w += t * w.w;
            }
        }

        #pragma unroll
        for (int rr = 0; rr < RPB; rr++) {
            int r = base + rr;
            if (r < Nn) {
                float4 o;
                o.x = fmaxf(acc[rr].x + b4.x, 0.f);
                o.y = fmaxf(acc[rr].y + b4.y, 0.f);
                o.z = fmaxf(acc[rr].z + b4.z, 0.f);
                o.w = fmaxf(acc[rr].w + b4.w, 0.f);
                ((float4*)g_h)[r * 32 + lane] = o;
            }
        }
        __syncwarp();
    }
}

// ---------------------------------------------------------------------------
// mm2: p = h @ W2    [N,128] -> [N,64]   (bias added in final kernel)
// Lane j computes output columns 2j..2j+1 (float2 accumulators).
// ---------------------------------------------------------------------------
__global__ __launch_bounds__(128) void mm2_k(const float* __restrict__ W2,
                                             int Nn) {
    __shared__ float sW2[D1 * D0];          // 32 KB, row-major [k][j]
    __shared__ float sh[4][RPB][D1];        // staged h rows, 16 KB

    int tid = threadIdx.x;
    for (int i = tid; i < D1 * D0; i += blockDim.x) sW2[i] = W2[i];
    __syncthreads();

    int warp = tid >> 5, lane = tid & 31;
    int nwarps = gridDim.x * 4;
    int gw = blockIdx.x * 4 + warp;

    for (int base = gw * RPB; base < Nn; base += nwarps * RPB) {
        #pragma unroll
        for (int rr = 0; rr < RPB; rr++) {
            int r = base + rr;
            if (r < Nn)
                ((float4*)sh[warp][rr])[lane] = ((const float4*)g_h)[r * 32 + lane];
        }
        __syncwarp();

        float2 acc[RPB];
        #pragma unroll
        for (int rr = 0; rr < RPB; rr++) acc[rr] = make_float2(0.f, 0.f);

        #pragma unroll 4
        for (int k = 0; k < D1; k++) {
            float2 w = ((const float2*)sW2)[k * 32 + lane];
            #pragma unroll
            for (int rr = 0; rr < RPB; rr++) {
                float hk = sh[warp][rr][k];
                acc[rr].x += hk * w.x;
                acc[rr].y += hk * w.y;
            }
        }

        #pragma unroll
        for (int rr = 0; rr < RPB; rr++) {
            int r = base + rr;
            if (r < Nn) ((float2*)g_p)[r * 32 + lane] = acc[rr];
        }
        __syncwarp();
    }
}

// ---------------------------------------------------------------------------
// final: out = agg2/deg + p + b2
// ---------------------------------------------------------------------------
__global__ void final_k(const float* __restrict__ b2, float* __restrict__ out,
                        int Nn) {
    int tid = blockIdx.x * blockDim.x + threadIdx.x;
    if (tid >= Nn * 16) return;
    int n = tid >> 4;
    int c = tid & 15;
    float inv = 1.0f / fmaxf(g_deg[n], 1.0f);
    float4 a = ((const float4*)g_agg2)[tid];
    float4 p = ((const float4*)g_p)[tid];
    float4 b = __ldg(&((const float4*)b2)[c]);
    float4 o;
    o.x = a.x * inv + p.x + b.x;
    o.y = a.y * inv + p.y + b.y;
    o.z = a.z * inv + p.z + b.z;
    o.w = a.w * inv + p.w + b.w;
    ((float4*)out)[tid] = o;
}

// ---------------------------------------------------------------------------
extern "C" void kernel_launch(void* const* d_in, const int* in_sizes, int n_in,
                              void* d_out, int out_size) {
    const float* x   = (const float*)d_in[0];
    const void*  ei  = d_in[1];
    const float* W1  = (const float*)d_in[2];
    const float* b1  = (const float*)d_in[3];
    const float* W2  = (const float*)d_in[4];
    const float* b2  = (const float*)d_in[5];
    float*       out = (float*)d_out;

    int Nn = in_sizes[0] / D0;       // 100000
    int E  = in_sizes[1] / 2;        // 1600000

    // 0. normalize edge indices to int32 (dtype auto-detect)
    detect_k<<<1, 256>>>((const int*)ei, 2 * E * 2);
    convert_k<<<(2 * E + 255) / 256, 256>>>(ei, 2 * E);

    // 1. zero scratch
    zero_k<<<(Nn * 16 + 255) / 256, 256>>>(Nn);

    // 2. scatter x -> agg1 (+deg)
    {
        long long thr = (long long)E * 16;
        scatter1_k<<<(unsigned)((thr + 255) / 256), 256>>>((const float4*)x, E);
    }
    // 3. h = relu((agg1/deg + x) @ W1 + b1)
    mm1_k<<<592, 128>>>(x, W1, b1, Nn);
    // 4. p = h @ W2
    mm2_k<<<592, 128>>>(W2, Nn);
    // 5. scatter p -> agg2
    {
        long long thr = (long long)E * 16;
        scatter2_k<<<(unsigned)((thr + 255) / 256), 256>>>(E);
    }
    // 6. out = agg2/deg + p + b2
    final_k<<<(Nn * 16 + 255) / 256, 256>>>(b2, out, Nn);
}

// round 3
// speedup vs baseline: 1.4849x; 1.4849x over previous
#include <cuda_runtime.h>

#define D0 64
#define D1 128
#define NMAX 100000
#define EMAX 1600000
#define RPB 8

// Scratch (device globals; allocation in kernel_launch is forbidden)
__device__ __align__(16) float g_t[NMAX * D0];       // 25.6 MB  (agg1/deg + x)
__device__ __align__(16) float g_h[NMAX * D1];       // 51.2 MB  (relu layer-1 out)
__device__ __align__(16) float g_p[NMAX * D0];       // 25.6 MB  (h @ W2)
__device__ __align__(16) int   g_idx[2 * EMAX];      // 12.8 MB  (row, col int32)
__device__ __align__(16) int   g_col[EMAX];          // 6.4 MB   (CSR col indices)
__device__ int g_rowptr[NMAX + 1];
__device__ int g_cur[NMAX];
__device__ int g_cnt[NMAX];
__device__ int g_bsum[128];
__device__ int g_boff[128];
__device__ int g_is64;

// ---------------------------------------------------------------------------
// Detect int64 vs int32 edge_index delivery (odd 32-bit words all zero = i64)
// ---------------------------------------------------------------------------
__global__ void detect_k(const int* __restrict__ ei_raw, int total_i32) {
    __shared__ int any_nz;
    if (threadIdx.x == 0) any_nz = 0;
    __syncthreads();
    int limit = total_i32 < 8192 ? total_i32 : 8192;
    for (int i = 2 * threadIdx.x + 1; i < limit; i += 2 * blockDim.x)
        if (ei_raw[i] != 0) any_nz = 1;
    __syncthreads();
    if (threadIdx.x == 0) g_is64 = any_nz ? 0 : 1;
}

__global__ void zero_cnt_k(int Nn) {
    int i = blockIdx.x * blockDim.x + threadIdx.x;
    if (i < Nn) g_cnt[i] = 0;
}

// ---------------------------------------------------------------------------
// Normalize indices to int32 + fused row histogram
// ---------------------------------------------------------------------------
__global__ void convert_k(const void* __restrict__ ei, int E) {
    int i = blockIdx.x * blockDim.x + threadIdx.x;
    if (i >= 2 * E) return;
    int v = g_is64 ? (int)((const long long*)ei)[i] : ((const int*)ei)[i];
    g_idx[i] = v;
    if (i < E) atomicAdd(&g_cnt[v], 1);
}

// ---------------------------------------------------------------------------
// 3-kernel exclusive prefix scan of g_cnt -> g_rowptr
// ---------------------------------------------------------------------------
__global__ void scan1_k(int Nn) {
    __shared__ int sh[1024];
    int g = blockIdx.x * 1024 + threadIdx.x;
    int v = (g < Nn) ? g_cnt[g] : 0;
    sh[threadIdx.x] = v;
    __syncthreads();
    #pragma unroll
    for (int off = 1; off < 1024; off <<= 1) {
        int t = (threadIdx.x >= off) ? sh[threadIdx.x - off] : 0;
        __syncthreads();
        sh[threadIdx.x] += t;
        __syncthreads();
    }
    if (g < Nn) g_rowptr[g] = sh[threadIdx.x] - v;   // exclusive within block
    if (threadIdx.x == 1023) g_bsum[blockIdx.x] = sh[1023];
}

__global__ void scan2_k(int nblk) {
    __shared__ int sh[128];
    int t = threadIdx.x;
    sh[t] = (t < nblk) ? g_bsum[t] : 0;
    __syncthreads();
    #pragma unroll
    for (int off = 1; off < 128; off <<= 1) {
        int v = (t >= off) ? sh[t - off] : 0;
        __syncthreads();
        sh[t] += v;
        __syncthreads();
    }
    if (t < nblk) g_boff[t] = (t == 0) ? 0 : sh[t - 1];  // exclusive
}

__global__ void scan3_k(int Nn, int E) {
    int g = blockIdx.x * 1024 + threadIdx.x;
    if (g < Nn) {
        int v = g_rowptr[g] + g_boff[blockIdx.x];
        g_rowptr[g] = v;
        g_cur[g] = v;
    }
    if (g == 0) g_rowptr[Nn] = E;
}

// ---------------------------------------------------------------------------
// CSR fill: place col index of each edge into its row's segment
// ---------------------------------------------------------------------------
__global__ void fill_k(int E) {
    int e = blockIdx.x * blockDim.x + threadIdx.x;
    if (e >= E) return;
    int r = g_idx[e];
    int c = g_idx[e + E];
    int pos = atomicAdd(&g_cur[r], 1);
    g_col[pos] = c;
}

// ---------------------------------------------------------------------------
// agg1: t[r] = (sum_{c in adj(r)} x[c]) / max(deg,1) + x[r]
// One warp per row; lane handles 2 floats (float2). Neighbor x rows are
// 256B contiguous -> perfectly coalesced 32-lane float2 loads.
// ---------------------------------------------------------------------------
__global__ __launch_bounds__(512) void agg1_k(const float* __restrict__ x, int Nn) {
    int w = (blockIdx.x * blockDim.x + threadIdx.x) >> 5;
    if (w >= Nn) return;
    int lane = threadIdx.x & 31;
    int s = g_rowptr[w], e = g_rowptr[w + 1];
    float2 acc = make_float2(0.f, 0.f);
    int j = s;
    #pragma unroll 1
    for (; j + 4 <= e; j += 4) {
        int c0 = g_col[j], c1 = g_col[j + 1], c2 = g_col[j + 2], c3 = g_col[j + 3];
        float2 v0 = __ldg(&((const float2*)x)[c0 * 32 + lane]);
        float2 v1 = __ldg(&((const float2*)x)[c1 * 32 + lane]);
        float2 v2 = __ldg(&((const float2*)x)[c2 * 32 + lane]);
        float2 v3 = __ldg(&((const float2*)x)[c3 * 32 + lane]);
        acc.x += v0.x + v1.x + v2.x + v3.x;
        acc.y += v0.y + v1.y + v2.y + v3.y;
    }
    for (; j < e; j++) {
        int c = g_col[j];
        float2 v = __ldg(&((const float2*)x)[c * 32 + lane]);
        acc.x += v.x;
        acc.y += v.y;
    }
    float inv = 1.0f / fmaxf((float)(e - s), 1.0f);
    float2 xx = __ldg(&((const float2*)x)[w * 32 + lane]);
    ((float2*)g_t)[w * 32 + lane] = make_float2(acc.x * inv + xx.x, acc.y * inv + xx.y);
}

// ---------------------------------------------------------------------------
// agg2: out[r] = (sum_{c in adj(r)} p[c]) / max(deg,1) + p[r] + b2
// ---------------------------------------------------------------------------
__global__ __launch_bounds__(512) void agg2_k(const float* __restrict__ b2,
                                              float* __restrict__ out, int Nn) {
    int w = (blockIdx.x * blockDim.x + threadIdx.x) >> 5;
    if (w >= Nn) return;
    int lane = threadIdx.x & 31;
    int s = g_rowptr[w], e = g_rowptr[w + 1];
    float2 acc = make_float2(0.f, 0.f);
    int j = s;
    #pragma unroll 1
    for (; j + 4 <= e; j += 4) {
        int c0 = g_col[j], c1 = g_col[j + 1], c2 = g_col[j + 2], c3 = g_col[j + 3];
        float2 v0 = ((const float2*)g_p)[c0 * 32 + lane];
        float2 v1 = ((const float2*)g_p)[c1 * 32 + lane];
        float2 v2 = ((const float2*)g_p)[c2 * 32 + lane];
        float2 v3 = ((const float2*)g_p)[c3 * 32 + lane];
        acc.x += v0.x + v1.x + v2.x + v3.x;
        acc.y += v0.y + v1.y + v2.y + v3.y;
    }
    for (; j < e; j++) {
        int c = g_col[j];
        float2 v = ((const float2*)g_p)[c * 32 + lane];
        acc.x += v.x;
        acc.y += v.y;
    }
    float inv = 1.0f / fmaxf((float)(e - s), 1.0f);
    float2 pp = ((const float2*)g_p)[w * 32 + lane];
    float2 bb = __ldg(&((const float2*)b2)[lane]);
    ((float2*)out)[w * 32 + lane] =
        make_float2(acc.x * inv + pp.x + bb.x, acc.y * inv + pp.y + bb.y);
}

// ---------------------------------------------------------------------------
// mm1: h = relu(t @ W1 + b1)   [N,64] -> [N,128]
// ---------------------------------------------------------------------------
__global__ __launch_bounds__(128) void mm1_k(const float* __restrict__ W1,
                                             const float* __restrict__ b1,
                                             int Nn) {
    __shared__ float sW1[D0 * D1];
    __shared__ float sb1[D1];
    __shared__ float st[4][RPB][D0];

    int tid = threadIdx.x;
    for (int i = tid; i < D0 * D1; i += blockDim.x) sW1[i] = W1[i];
    if (tid < D1) sb1[tid] = b1[tid];
    __syncthreads();

    int warp = tid >> 5, lane = tid & 31;
    int nwarps = gridDim.x * 4;
    int gw = blockIdx.x * 4 + warp;
    float4 b4 = ((const float4*)sb1)[lane];

    for (int base = gw * RPB; base < Nn; base += nwarps * RPB) {
        #pragma unroll
        for (int rr = 0; rr < RPB; rr++) {
            int r = base + rr;
            if (r < Nn)
                ((float2*)st[warp][rr])[lane] = ((const float2*)g_t)[r * 32 + lane];
        }
        __syncwarp();

        float4 acc[RPB];
        #pragma unroll
        for (int rr = 0; rr < RPB; rr++) acc[rr] = make_float4(0.f, 0.f, 0.f, 0.f);

        #pragma unroll 4
        for (int k = 0; k < D0; k++) {
            float4 w = ((const float4*)sW1)[k * 32 + lane];
            #pragma unroll
            for (int rr = 0; rr < RPB; rr++) {
                float t = st[warp][rr][k];
                acc[rr].x += t * w.x;
                acc[rr].y += t * w.y;
                acc[rr].z += t * w.z;
                acc[rr].w += t * w.w;
            }
        }

        #pragma unroll
        for (int rr = 0; rr < RPB; rr++) {
            int r = base + rr;
            if (r < Nn) {
                float4 o;
                o.x = fmaxf(acc[rr].x + b4.x, 0.f);
                o.y = fmaxf(acc[rr].y + b4.y, 0.f);
                o.z = fmaxf(acc[rr].z + b4.z, 0.f);
                o.w = fmaxf(acc[rr].w + b4.w, 0.f);
                ((float4*)g_h)[r * 32 + lane] = o;
            }
        }
        __syncwarp();
    }
}

// ---------------------------------------------------------------------------
// mm2: p = h @ W2   [N,128] -> [N,64]  (bias fused into agg2)
// ---------------------------------------------------------------------------
__global__ __launch_bounds__(128) void mm2_k(const float* __restrict__ W2,
                                             int Nn) {
    __shared__ float sW2[D1 * D0];
    __shared__ float sh[4][RPB][D1];

    int tid = threadIdx.x;
    for (int i = tid; i < D1 * D0; i += blockDim.x) sW2[i] = W2[i];
    __syncthreads();

    int warp = tid >> 5, lane = tid & 31;
    int nwarps = gridDim.x * 4;
    int gw = blockIdx.x * 4 + warp;

    for (int base = gw * RPB; base < Nn; base += nwarps * RPB) {
        #pragma unroll
        for (int rr = 0; rr < RPB; rr++) {
            int r = base + rr;
            if (r < Nn)
                ((float4*)sh[warp][rr])[lane] = ((const float4*)g_h)[r * 32 + lane];
        }
        __syncwarp();

        float2 acc[RPB];
        #pragma unroll
        for (int rr = 0; rr < RPB; rr++) acc[rr] = make_float2(0.f, 0.f);

        #pragma unroll 4
        for (int k = 0; k < D1; k++) {
            float2 w = ((const float2*)sW2)[k * 32 + lane];
            #pragma unroll
            for (int rr = 0; rr < RPB; rr++) {
                float hk = sh[warp][rr][k];
                acc[rr].x += hk * w.x;
                acc[rr].y += hk * w.y;
            }
        }

        #pragma unroll
        for (int rr = 0; rr < RPB; rr++) {
            int r = base + rr;
            if (r < Nn) ((float2*)g_p)[r * 32 + lane] = acc[rr];
        }
        __syncwarp();
    }
}

// ---------------------------------------------------------------------------
extern "C" void kernel_launch(void* const* d_in, const int* in_sizes, int n_in,
                              void* d_out, int out_size) {
    const void*  ei  = d_in[1];
    const float* x   = (const float*)d_in[0];
    const float* W1  = (const float*)d_in[2];
    const float* b1  = (const float*)d_in[3];
    const float* W2  = (const float*)d_in[4];
    const float* b2  = (const float*)d_in[5];
    float*       out = (float*)d_out;

    int Nn = in_sizes[0] / D0;       // 100000
    int E  = in_sizes[1] / 2;        // 1600000
    int nblk_scan = (Nn + 1023) / 1024;

    // --- CSR build ---
    detect_k<<<1, 256>>>((const int*)ei, 2 * E * 2);
    zero_cnt_k<<<(Nn + 255) / 256, 256>>>(Nn);
    convert_k<<<(2 * E + 255) / 256, 256>>>(ei, E);
    scan1_k<<<nblk_scan, 1024>>>(Nn);
    scan2_k<<<1, 128>>>(nblk_scan);
    scan3_k<<<nblk_scan, 1024>>>(Nn, E);
    fill_k<<<(E + 255) / 256, 256>>>(E);

    // --- layer 1 ---
    agg1_k<<<(Nn * 32 + 511) / 512, 512>>>(x, Nn);
    mm1_k<<<592, 128>>>(W1, b1, Nn);

    // --- layer 2 ---
    mm2_k<<<592, 128>>>(W2, Nn);
    agg2_k<<<(Nn * 32 + 511) / 512, 512>>>(b2, out, Nn);
}

// round 4
// speedup vs baseline: 1.5194x; 1.0233x over previous
#include <cuda_runtime.h>
#include <cstdint>

#define D0 64
#define D1 128
#define NMAX 100000
#define EMAX 1600000
#define RPB 8

// Scratch (device globals; allocation in kernel_launch is forbidden)
__device__ __align__(16) float g_t[NMAX * D0];       // 25.6 MB  (agg1/deg + x)
__device__ __align__(16) float g_h[NMAX * D1];       // 51.2 MB  (relu layer-1 out)
__device__ __align__(16) float g_p[NMAX * D0];       // 25.6 MB  (h @ W2)
__device__ __align__(16) int   g_idx[2 * EMAX];      // 12.8 MB  (row, col int32)
__device__ __align__(16) int   g_col[EMAX];          // 6.4 MB   (CSR col indices)
__device__ int g_rowptr[NMAX + 1];
__device__ int g_cur[NMAX];
__device__ int g_cnt[NMAX];
__device__ int g_bsum[128];
__device__ int g_boff[128];
__device__ int g_is64;

// packed f32x2 FMA: d = a*b + d  (each half is IEEE fp32)
__device__ __forceinline__ void fma2(uint64_t& d, uint64_t a, uint64_t b) {
    asm("fma.rn.f32x2 %0, %1, %2, %0;" : "+l"(d) : "l"(a), "l"(b));
}
__device__ __forceinline__ uint64_t pack2(float v) {
    uint32_t u = __float_as_uint(v);
    uint64_t r;
    asm("mov.b64 %0, {%1, %1};" : "=l"(r) : "r"(u));
    return r;
}

// ---------------------------------------------------------------------------
// prep: zero g_cnt (all blocks) + detect int64 vs int32 edges (block 0)
// ---------------------------------------------------------------------------
__global__ void prep_k(const int* __restrict__ ei_raw, int total_i32, int Nn) {
    int i = blockIdx.x * blockDim.x + threadIdx.x;
    if (i < Nn) g_cnt[i] = 0;
    if (blockIdx.x == 0) {
        __shared__ int any_nz;
        if (threadIdx.x == 0) any_nz = 0;
        __syncthreads();
        int limit = total_i32 < 8192 ? total_i32 : 8192;
        for (int k = 2 * threadIdx.x + 1; k < limit; k += 2 * blockDim.x)
            if (ei_raw[k] != 0) any_nz = 1;
        __syncthreads();
        if (threadIdx.x == 0) g_is64 = any_nz ? 0 : 1;
    }
}

// ---------------------------------------------------------------------------
// Normalize indices to int32 + fused row histogram
// ---------------------------------------------------------------------------
__global__ void convert_k(const void* __restrict__ ei, int E) {
    int i = blockIdx.x * blockDim.x + threadIdx.x;
    if (i >= 2 * E) return;
    int v = g_is64 ? (int)((const long long*)ei)[i] : ((const int*)ei)[i];
    g_idx[i] = v;
    if (i < E) atomicAdd(&g_cnt[v], 1);
}

// ---------------------------------------------------------------------------
// 3-kernel exclusive prefix scan of g_cnt -> g_rowptr
// ---------------------------------------------------------------------------
__global__ void scan1_k(int Nn) {
    __shared__ int sh[1024];
    int g = blockIdx.x * 1024 + threadIdx.x;
    int v = (g < Nn) ? g_cnt[g] : 0;
    sh[threadIdx.x] = v;
    __syncthreads();
    #pragma unroll
    for (int off = 1; off < 1024; off <<= 1) {
        int t = (threadIdx.x >= off) ? sh[threadIdx.x - off] : 0;
        __syncthreads();
        sh[threadIdx.x] += t;
        __syncthreads();
    }
    if (g < Nn) g_rowptr[g] = sh[threadIdx.x] - v;
    if (threadIdx.x == 1023) g_bsum[blockIdx.x] = sh[1023];
}

__global__ void scan2_k(int nblk) {
    __shared__ int sh[128];
    int t = threadIdx.x;
    sh[t] = (t < nblk) ? g_bsum[t] : 0;
    __syncthreads();
    #pragma unroll
    for (int off = 1; off < 128; off <<= 1) {
        int v = (t >= off) ? sh[t - off] : 0;
        __syncthreads();
        sh[t] += v;
        __syncthreads();
    }
    if (t < nblk) g_boff[t] = (t == 0) ? 0 : sh[t - 1];
}

__global__ void scan3_k(int Nn, int E) {
    int g = blockIdx.x * 1024 + threadIdx.x;
    if (g < Nn) {
        int v = g_rowptr[g] + g_boff[blockIdx.x];
        g_rowptr[g] = v;
        g_cur[g] = v;
    }
    if (g == 0) g_rowptr[Nn] = E;
}

// ---------------------------------------------------------------------------
// CSR fill
// ---------------------------------------------------------------------------
__global__ void fill_k(int E) {
    int e = blockIdx.x * blockDim.x + threadIdx.x;
    if (e >= E) return;
    int r = g_idx[e];
    int c = g_idx[e + E];
    int pos = atomicAdd(&g_cur[r], 1);
    g_col[pos] = c;
}

// ---------------------------------------------------------------------------
// agg1: t[r] = (sum_{c in adj(r)} x[c]) / max(deg,1) + x[r]
// ---------------------------------------------------------------------------
__global__ __launch_bounds__(512) void agg1_k(const float* __restrict__ x, int Nn) {
    int w = (blockIdx.x * blockDim.x + threadIdx.x) >> 5;
    if (w >= Nn) return;
    int lane = threadIdx.x & 31;
    int s = g_rowptr[w], e = g_rowptr[w + 1];
    float2 acc = make_float2(0.f, 0.f);
    int j = s;
    #pragma unroll 1
    for (; j + 4 <= e; j += 4) {
        int c0 = g_col[j], c1 = g_col[j + 1], c2 = g_col[j + 2], c3 = g_col[j + 3];
        float2 v0 = __ldg(&((const float2*)x)[c0 * 32 + lane]);
        float2 v1 = __ldg(&((const float2*)x)[c1 * 32 + lane]);
        float2 v2 = __ldg(&((const float2*)x)[c2 * 32 + lane]);
        float2 v3 = __ldg(&((const float2*)x)[c3 * 32 + lane]);
        acc.x += v0.x + v1.x + v2.x + v3.x;
        acc.y += v0.y + v1.y + v2.y + v3.y;
    }
    for (; j < e; j++) {
        int c = g_col[j];
        float2 v = __ldg(&((const float2*)x)[c * 32 + lane]);
        acc.x += v.x;
        acc.y += v.y;
    }
    float inv = 1.0f / fmaxf((float)(e - s), 1.0f);
    float2 xx = __ldg(&((const float2*)x)[w * 32 + lane]);
    ((float2*)g_t)[w * 32 + lane] = make_float2(acc.x * inv + xx.x, acc.y * inv + xx.y);
}

// ---------------------------------------------------------------------------
// agg2: out[r] = (sum_{c in adj(r)} p[c]) / max(deg,1) + p[r] + b2
// ---------------------------------------------------------------------------
__global__ __launch_bounds__(512) void agg2_k(const float* __restrict__ b2,
                                              float* __restrict__ out, int Nn) {
    int w = (blockIdx.x * blockDim.x + threadIdx.x) >> 5;
    if (w >= Nn) return;
    int lane = threadIdx.x & 31;
    int s = g_rowptr[w], e = g_rowptr[w + 1];
    float2 acc = make_float2(0.f, 0.f);
    int j = s;
    #pragma unroll 1
    for (; j + 4 <= e; j += 4) {
        int c0 = g_col[j], c1 = g_col[j + 1], c2 = g_col[j + 2], c3 = g_col[j + 3];
        float2 v0 = ((const float2*)g_p)[c0 * 32 + lane];
        float2 v1 = ((const float2*)g_p)[c1 * 32 + lane];
        float2 v2 = ((const float2*)g_p)[c2 * 32 + lane];
        float2 v3 = ((const float2*)g_p)[c3 * 32 + lane];
        acc.x += v0.x + v1.x + v2.x + v3.x;
        acc.y += v0.y + v1.y + v2.y + v3.y;
    }
    for (; j < e; j++) {
        int c = g_col[j];
        float2 v = ((const float2*)g_p)[c * 32 + lane];
        acc.x += v.x;
        acc.y += v.y;
    }
    float inv = 1.0f / fmaxf((float)(e - s), 1.0f);
    float2 pp = ((const float2*)g_p)[w * 32 + lane];
    float2 bb = __ldg(&((const float2*)b2)[lane]);
    ((float2*)out)[w * 32 + lane] =
        make_float2(acc.x * inv + pp.x + bb.x, acc.y * inv + pp.y + bb.y);
}

// ---------------------------------------------------------------------------
// mm1: h = relu(t @ W1 + b1)  [N,64]->[N,128], packed f32x2 FMA inner loop.
// Lane j owns output cols 4j..4j+3 as two f32x2 accumulators.
// ---------------------------------------------------------------------------
__global__ __launch_bounds__(128) void mm1_k(const float* __restrict__ W1,
                                             const float* __restrict__ b1,
                                             int Nn) {
    __shared__ float sW1[D0 * D1];
    __shared__ float sb1[D1];
    __shared__ float st[4][RPB][D0];

    int tid = threadIdx.x;
    for (int i = tid; i < D0 * D1; i += blockDim.x) sW1[i] = W1[i];
    if (tid < D1) sb1[tid] = b1[tid];
    __syncthreads();

    int warp = tid >> 5, lane = tid & 31;
    int nwarps = gridDim.x * 4;
    int gw = blockIdx.x * 4 + warp;
    float4 b4 = ((const float4*)sb1)[lane];

    for (int base = gw * RPB; base < Nn; base += nwarps * RPB) {
        #pragma unroll
        for (int rr = 0; rr < RPB; rr++) {
            int r = base + rr;
            if (r < Nn)
                ((float2*)st[warp][rr])[lane] = ((const float2*)g_t)[r * 32 + lane];
        }
        __syncwarp();

        uint64_t accA[RPB], accB[RPB];
        #pragma unroll
        for (int rr = 0; rr < RPB; rr++) { accA[rr] = 0ull; accB[rr] = 0ull; }

        #pragma unroll 4
        for (int k = 0; k < D0; k++) {
            ulonglong2 w2 = ((const ulonglong2*)sW1)[k * 32 + lane];  // cols 4j..4j+3
            #pragma unroll
            for (int rr = 0; rr < RPB; rr++) {
                uint64_t tt = pack2(st[warp][rr][k]);
                fma2(accA[rr], tt, w2.x);
                fma2(accB[rr], tt, w2.y);
            }
        }

        #pragma unroll
        for (int rr = 0; rr < RPB; rr++) {
            int r = base + rr;
            if (r < Nn) {
                float2 a = *(float2*)&accA[rr];
                float2 b = *(float2*)&accB[rr];
                float4 o;
                o.x = fmaxf(a.x + b4.x, 0.f);
                o.y = fmaxf(a.y + b4.y, 0.f);
                o.z = fmaxf(b.x + b4.z, 0.f);
                o.w = fmaxf(b.y + b4.w, 0.f);
                ((float4*)g_h)[r * 32 + lane] = o;
            }
        }
        __syncwarp();
    }
}

// ---------------------------------------------------------------------------
// mm2: p = h @ W2  [N,128]->[N,64], packed f32x2 FMA.
// Lane j owns output cols 2j..2j+1 as one f32x2 accumulator.
// ---------------------------------------------------------------------------
__global__ __launch_bounds__(128) void mm2_k(const float* __restrict__ W2,
                                             int Nn) {
    __shared__ float sW2[D1 * D0];
    __shared__ float sh[4][RPB][D1];

    int tid = threadIdx.x;
    for (int i = tid; i < D1 * D0; i += blockDim.x) sW2[i] = W2[i];
    __syncthreads();

    int warp = tid >> 5, lane = tid & 31;
    int nwarps = gridDim.x * 4;
    int gw = blockIdx.x * 4 + warp;

    for (int base = gw * RPB; base < Nn; base += nwarps * RPB) {
        #pragma unroll
        for (int rr = 0; rr < RPB; rr++) {
            int r = base + rr;
            if (r < Nn)
                ((float4*)sh[warp][rr])[lane] = ((const float4*)g_h)[r * 32 + lane];
        }
        __syncwarp();

        uint64_t acc[RPB];
        #pragma unroll
        for (int rr = 0; rr < RPB; rr++) acc[rr] = 0ull;

        #pragma unroll 4
        for (int k = 0; k < D1; k++) {
            uint64_t w = ((const uint64_t*)sW2)[k * 32 + lane];  // cols 2j,2j+1
            #pragma unroll
            for (int rr = 0; rr < RPB; rr++) {
                uint64_t hh = pack2(sh[warp][rr][k]);
                fma2(acc[rr], hh, w);
            }
        }

        #pragma unroll
        for (int rr = 0; rr < RPB; rr++) {
            int r = base + rr;
            if (r < Nn) ((float2*)g_p)[r * 32 + lane] = *(float2*)&acc[rr];
        }
        __syncwarp();
    }
}

// ---------------------------------------------------------------------------
extern "C" void kernel_launch(void* const* d_in, const int* in_sizes, int n_in,
                              void* d_out, int out_size) {
    const float* x   = (const float*)d_in[0];
    const void*  ei  = d_in[1];
    const float* W1  = (const float*)d_in[2];
    const float* b1  = (const float*)d_in[3];
    const float* W2  = (const float*)d_in[4];
    const float* b2  = (const float*)d_in[5];
    float*       out = (float*)d_out;

    int Nn = in_sizes[0] / D0;       // 100000
    int E  = in_sizes[1] / 2;        // 1600000
    int nblk_scan = (Nn + 1023) / 1024;

    // --- CSR build ---
    prep_k<<<(Nn + 255) / 256, 256>>>((const int*)ei, 2 * E * 2, Nn);
    convert_k<<<(2 * E + 255) / 256, 256>>>(ei, E);
    scan1_k<<<nblk_scan, 1024>>>(Nn);
    scan2_k<<<1, 128>>>(nblk_scan);
    scan3_k<<<nblk_scan, 1024>>>(Nn, E);
    fill_k<<<(E + 255) / 256, 256>>>(E);

    // --- layer 1 ---
    agg1_k<<<(Nn * 32 + 511) / 512, 512>>>(x, Nn);
    mm1_k<<<592, 128>>>(W1, b1, Nn);

    // --- layer 2 ---
    mm2_k<<<592, 128>>>(W2, Nn);
    agg2_k<<<(Nn * 32 + 511) / 512, 512>>>(b2, out, Nn);
}